// round 10
// baseline (speedup 1.0000x reference)
#include <cuda_runtime.h>
#include <cuda_bf16.h>
#include <math.h>
#include <stdint.h>

#define B_   16
#define M_   2048
#define E_   1024
#define H_   8
#define D_   128
#define MID_ 64
#define EPSV 1e-3f

// ---------------- scratch (device globals) ---------------------------------
__device__ float g_q[B_*H_*D_];
__device__ float g_v1[B_*H_*D_];
__device__ float g_masksum[B_];
__device__ float g_logits[B_*H_*M_];
__device__ float g_alpha[B_*H_*M_];
__device__ float g_poolpart[B_*H_*16*MID_];
__device__ float g_alpha_ch[B_*H_*D_];
__device__ float g_part[B_*H_*16*D_];
__device__ float g_v2[(size_t)B_*M_*E_];                 // 128 MiB normalized v2
// pre-converted bf16 hi/lo operands
__device__ __nv_bfloat16 g_keyHi[(size_t)B_*M_*E_];      // 64 MiB
__device__ __nv_bfloat16 g_keyLo[(size_t)B_*M_*E_];
__device__ __nv_bfloat16 g_v2iHi[(size_t)B_*M_*E_];
__device__ __nv_bfloat16 g_v2iLo[(size_t)B_*M_*E_];
__device__ __nv_bfloat16 g_WkTHi[E_*E_];                 // Wk^T  [n][k]
__device__ __nv_bfloat16 g_WkTLo[E_*E_];
__device__ __nv_bfloat16 g_Wv2THi[E_*E_];                // Wv2^T [n][k]
__device__ __nv_bfloat16 g_Wv2TLo[E_*E_];

// ---------------- helpers ---------------------------------------------------
__device__ __forceinline__ uint32_t smem_u32(const void* p) {
    uint32_t a;
    asm("{ .reg .u64 t; cvta.to.shared.u64 t, %1; cvt.u32.u64 %0, t; }"
        : "=r"(a) : "l"(p));
    return a;
}
__device__ __forceinline__ uint32_t packbf(__nv_bfloat16 a, __nv_bfloat16 b) {
    return (uint32_t)__bfloat16_as_ushort(a) |
           ((uint32_t)__bfloat16_as_ushort(b) << 16);
}

#define LDSM4(r0,r1,r2,r3,a) \
    asm volatile("ldmatrix.sync.aligned.m8n8.x4.shared.b16 {%0,%1,%2,%3}, [%4];" \
        : "=r"(r0), "=r"(r1), "=r"(r2), "=r"(r3) : "r"(a))

#define MMA16816(c, a, b0, b1) \
    asm volatile("mma.sync.aligned.m16n8k16.row.col.f32.bf16.bf16.f32 " \
        "{%0,%1,%2,%3},{%4,%5,%6,%7},{%8,%9},{%0,%1,%2,%3};" \
        : "+f"((c)[0]), "+f"((c)[1]), "+f"((c)[2]), "+f"((c)[3]) \
        : "r"((a)[0]), "r"((a)[1]), "r"((a)[2]), "r"((a)[3]), "r"(b0), "r"(b1))

#define CP16(dst, src) \
    asm volatile("cp.async.ca.shared.global [%0], [%1], 16;" \
                 :: "r"(dst), "l"(src) : "memory")
#define CP_COMMIT() asm volatile("cp.async.commit_group;" ::: "memory")
#define CP_WAIT(n)  asm volatile("cp.async.wait_group %0;" :: "n"(n) : "memory")

// staging tile layout: [128 rows][32 bf16] = 64B/row, XOR swizzle on 16B groups
__device__ __forceinline__ uint32_t sw_off(int r, int g) {
    return (uint32_t)(r*64 + ((g ^ ((r >> 1) & 3)) << 4));
}

// issue one chunk (K=32 slice) of A hi/lo + B hi/lo via cp.async
// stage layout: AHi +0, ALo +8192, BHi +16384, BLo +24576
__device__ __forceinline__ void issue_chunk(
    const __nv_bfloat16* __restrict__ AHi, const __nv_bfloat16* __restrict__ ALo,
    const __nv_bfloat16* __restrict__ BHi, const __nv_bfloat16* __restrict__ BLo,
    int ck, uint32_t st, int tid)
{
    #pragma unroll
    for (int u = 0; u < 2; u++) {
        const int idx = tid*2 + u;            // 0..511 16B-groups per tile
        const int r = idx >> 2, g = idx & 3;
        const uint32_t off = sw_off(r, g);
        const size_t gofs = (size_t)r*E_ + ck*32 + g*8;
        CP16(st +         off, AHi + gofs);
        CP16(st +  8192 + off, ALo + gofs);
        CP16(st + 16384 + off, BHi + gofs);
        CP16(st + 24576 + off, BLo + gofs);
    }
}

// ---------------------------------------------------------------------------
// split-bf16 tensor-core mainloop: C[128][128] = A[128x1024] @ BT[128x1024]^T
// 256 threads, warp w: wm=w&3 (32 rows), wn=w>>2 (64 cols); BK=32, 3 cp.async
// stages at sbR + s*32768.
// ---------------------------------------------------------------------------
__device__ __forceinline__ void mma_mainloop(
    const __nv_bfloat16* __restrict__ AHi, const __nv_bfloat16* __restrict__ ALo,
    const __nv_bfloat16* __restrict__ BHi, const __nv_bfloat16* __restrict__ BLo,
    uint32_t sbR, float c[2][8][4])
{
    const int tid = threadIdx.x;
    const int lane = tid & 31, w = tid >> 5;
    const int wm = w & 3, wn = w >> 2;
    const int qi = lane >> 3, ii = lane & 7;

    issue_chunk(AHi, ALo, BHi, BLo, 0, sbR,         tid); CP_COMMIT();
    issue_chunk(AHi, ALo, BHi, BLo, 1, sbR + 32768, tid); CP_COMMIT();

    for (int ck = 0; ck < 32; ck++) {
        if (ck + 2 < 32) {
            issue_chunk(AHi, ALo, BHi, BLo, ck + 2,
                        sbR + ((ck + 2) % 3)*32768, tid);
            CP_COMMIT();
        }
        const int rem = 31 - ck;
        if (rem >= 2)      { CP_WAIT(2); }
        else if (rem == 1) { CP_WAIT(1); }
        else               { CP_WAIT(0); }
        __syncthreads();

        const uint32_t st = sbR + (ck % 3)*32768;
        #pragma unroll
        for (int p = 0; p < 2; p++) {
            uint32_t ah[2][4], al[2][4], bh[4][4], bl[4][4];
            #pragma unroll
            for (int mt = 0; mt < 2; mt++) {
                const int r = wm*32 + mt*16 + ii + ((qi & 1) << 3);
                const int g = 2*p + (qi >> 1);
                const uint32_t off = sw_off(r, g);
                LDSM4(ah[mt][0], ah[mt][1], ah[mt][2], ah[mt][3], st + off);
                LDSM4(al[mt][0], al[mt][1], al[mt][2], al[mt][3], st + 8192 + off);
            }
            #pragma unroll
            for (int nb = 0; nb < 4; nb++) {
                const int r = wn*64 + nb*16 + ii + ((qi >> 1) << 3);
                const int g = 2*p + (qi & 1);
                const uint32_t off = sw_off(r, g);
                LDSM4(bh[nb][0], bh[nb][1], bh[nb][2], bh[nb][3], st + 16384 + off);
                LDSM4(bl[nb][0], bl[nb][1], bl[nb][2], bl[nb][3], st + 24576 + off);
            }
            #pragma unroll
            for (int mt = 0; mt < 2; mt++)
                #pragma unroll
                for (int nt = 0; nt < 8; nt++) {
                    const uint32_t* bhf = &bh[nt >> 1][(nt & 1)*2];
                    const uint32_t* blf = &bl[nt >> 1][(nt & 1)*2];
                    MMA16816(c[mt][nt], ah[mt], bhf[0], bhf[1]);
                    MMA16816(c[mt][nt], ah[mt], blf[0], blf[1]);
                    MMA16816(c[mt][nt], al[mt], bhf[0], bhf[1]);
                }
        }
        __syncthreads();
    }
}

// write fragments to Cs[128][132]
__device__ __forceinline__ void store_C(float* Cs, const float c[2][8][4], int tid)
{
    const int lane = tid & 31, w = tid >> 5;
    const int wm = w & 3, wn = w >> 2;
    const int rq = lane >> 2, cq = (lane & 3)*2;
    #pragma unroll
    for (int mt = 0; mt < 2; mt++)
        #pragma unroll
        for (int nt = 0; nt < 8; nt++) {
            const int m = wm*32 + mt*16 + rq;
            const int n = wn*64 + nt*8 + cq;
            Cs[m*132 + n]       = c[mt][nt][0];
            Cs[m*132 + n + 1]   = c[mt][nt][1];
            Cs[(m+8)*132 + n]   = c[mt][nt][2];
            Cs[(m+8)*132 + n+1] = c[mt][nt][3];
        }
}

// ---------------------------------------------------------------------------
// Kernel P: convert key/value2 fp32 -> bf16 hi/lo. grid (16384, 2), 256 thr.
// ---------------------------------------------------------------------------
__global__ void k_cvt_inputs(const float* __restrict__ key,
                             const float* __restrict__ value2)
{
    const int z = blockIdx.y;
    const float* src      = z ? value2 : key;
    __nv_bfloat16* hiD    = z ? g_v2iHi : g_keyHi;
    __nv_bfloat16* loD    = z ? g_v2iLo : g_keyLo;
    const size_t i = ((size_t)blockIdx.x*256 + threadIdx.x) * 8;
    const float4 v0 = *(const float4*)(src + i);
    const float4 v1 = *(const float4*)(src + i + 4);
    const float f[8] = {v0.x, v0.y, v0.z, v0.w, v1.x, v1.y, v1.z, v1.w};
    uint32_t hw[4], lw[4];
    #pragma unroll
    for (int j = 0; j < 4; j++) {
        const __nv_bfloat16 h0 = __float2bfloat16(f[2*j]);
        const __nv_bfloat16 h1 = __float2bfloat16(f[2*j+1]);
        hw[j] = packbf(h0, h1);
        lw[j] = packbf(__float2bfloat16(f[2*j]   - __bfloat162float(h0)),
                       __float2bfloat16(f[2*j+1] - __bfloat162float(h1)));
    }
    *(uint4*)(hiD + i) = make_uint4(hw[0], hw[1], hw[2], hw[3]);
    *(uint4*)(loD + i) = make_uint4(lw[0], lw[1], lw[2], lw[3]);
}

// ---------------------------------------------------------------------------
// Kernel 0: weight transpose + bf16 hi/lo split. grid (32,32,2), block (32,8)
// ---------------------------------------------------------------------------
__global__ void k_transpose(const float* __restrict__ Wk,
                            const float* __restrict__ Wv2)
{
    __shared__ float t[32][33];
    const int z = blockIdx.z;
    const float* S        = (z == 0) ? Wk : Wv2;
    __nv_bfloat16* hiD    = (z == 0) ? g_WkTHi : g_Wv2THi;
    __nv_bfloat16* loD    = (z == 0) ? g_WkTLo : g_Wv2TLo;
    const int r0 = blockIdx.y * 32, c0 = blockIdx.x * 32;
    const int tx = threadIdx.x, ty = threadIdx.y;
    #pragma unroll
    for (int i = 0; i < 4; i++)
        t[ty + 8*i][tx] = S[(size_t)(r0 + ty + 8*i)*E_ + c0 + tx];
    __syncthreads();
    #pragma unroll
    for (int i = 0; i < 4; i++) {
        const float x = t[tx][ty + 8*i];
        const __nv_bfloat16 h = __float2bfloat16(x);
        const size_t idx = (size_t)(c0 + ty + 8*i)*E_ + r0 + tx;
        hiD[idx] = h;
        loD[idx] = __float2bfloat16(x - __bfloat162float(h));
    }
}

// ---------------------------------------------------------------------------
// Kernel 1: q/v1 small projections + masksum (unchanged)
// ---------------------------------------------------------------------------
__global__ void k_smallproj(const float* __restrict__ query,
                            const float* __restrict__ value1,
                            const float* __restrict__ mask,
                            const float* __restrict__ Wq, const float* __restrict__ bq,
                            const float* __restrict__ gq, const float* __restrict__ Bq,
                            const float* __restrict__ Wv1, const float* __restrict__ bv1,
                            const float* __restrict__ gv1, const float* __restrict__ Bv1)
{
    __shared__ float xs[E_];
    __shared__ float ys[E_];
    __shared__ float red[8];
    const int blk   = blockIdx.x;
    const int which = blk >> 4;
    const int r     = blk & 15;
    const float* x    = which ? value1 : query;
    const float* W    = which ? Wv1 : Wq;
    const float* bias = which ? bv1 : bq;
    const float* gam  = which ? gv1 : gq;
    const float* bet  = which ? Bv1 : Bq;
    float* dst        = which ? g_v1 : g_q;
    const int tid = threadIdx.x;

    #pragma unroll
    for (int c = 0; c < 4; c++) xs[tid + 256*c] = x[r*E_ + tid + 256*c];
    __syncthreads();

    float a0 = bias[tid], a1 = bias[tid+256], a2 = bias[tid+512], a3 = bias[tid+768];
    #pragma unroll 4
    for (int k = 0; k < E_; k++) {
        const float xv = xs[k];
        const float* wr = W + (size_t)k*E_ + tid;
        a0 += xv*wr[0]; a1 += xv*wr[256]; a2 += xv*wr[512]; a3 += xv*wr[768];
    }
    a0 = a0 > 0.f ? a0 : expm1f(a0);
    a1 = a1 > 0.f ? a1 : expm1f(a1);
    a2 = a2 > 0.f ? a2 : expm1f(a2);
    a3 = a3 > 0.f ? a3 : expm1f(a3);
    ys[tid] = a0; ys[tid+256] = a1; ys[tid+512] = a2; ys[tid+768] = a3;
    __syncthreads();

    const int w = tid >> 5, lane = tid & 31;
    float v[4]; float s = 0.f, sq = 0.f;
    #pragma unroll
    for (int c = 0; c < 4; c++) {
        v[c] = ys[w*128 + lane + 32*c];
        s += v[c]; sq += v[c]*v[c];
    }
    #pragma unroll
    for (int o = 16; o > 0; o >>= 1) {
        s  += __shfl_xor_sync(0xffffffffu, s,  o);
        sq += __shfl_xor_sync(0xffffffffu, sq, o);
    }
    const float mu  = s * (1.f/128.f);
    const float var = sq * (1.f/128.f) - mu*mu;
    const float rs  = rsqrtf(var + EPSV);
    #pragma unroll
    for (int c = 0; c < 4; c++) {
        const int d = lane + 32*c;
        const int e = w*128 + d;
        dst[(r*8 + w)*128 + d] = (v[c]-mu)*rs*gam[e] + bet[e];
    }

    if (which == 0) {
        float ms = 0.f;
        #pragma unroll
        for (int i = 0; i < 8; i++) ms += mask[r*M_ + tid + 256*i];
        #pragma unroll
        for (int o = 16; o > 0; o >>= 1) ms += __shfl_xor_sync(0xffffffffu, ms, o);
        if (lane == 0) red[w] = ms;
        __syncthreads();
        if (tid == 0) {
            float t = 0.f;
            #pragma unroll
            for (int i = 0; i < 8; i++) t += red[i];
            g_masksum[r] = t;
        }
    }
}

// ---------------------------------------------------------------------------
// Kernel 2: K path (tensor-core GEMM + fused epilogue)
// smem: [Cs 128*132 | aS 128*129 | WbS 128*68]; cp.async staging [0,98304)
// aliases Cs/aS prefix (dead during mainloop).
// ---------------------------------------------------------------------------
__global__ void __launch_bounds__(256) k_kpath(
    const float* __restrict__ bk,  const float* __restrict__ gk,
    const float* __restrict__ Bk,  const float* __restrict__ mask,
    const float* __restrict__ Wb,  const float* __restrict__ bb,
    const float* __restrict__ Wl1, const float* __restrict__ bl1)
{
    extern __shared__ float smf[];
    float* Cs  = smf;                          // 16896 floats
    float* aS  = smf + 16896;                  // 16512 floats (pitch 129)
    float* WbS = smf + 16896 + 16512;          // 8704 floats (pitch 68)
    const uint32_t sbR = smem_u32(smf);

    const int tid = threadIdx.x;
    const int tx = tid & 15, ty = tid >> 4;
    const int h = blockIdx.x;
    const int rowBase = blockIdx.y * 128;
    const int b    = rowBase >> 11;
    const int tile = (rowBase >> 7) & 15;
    const int bh = b*8 + h;

    for (int i = tid; i < 128*64; i += 256)
        WbS[(i>>6)*68 + (i&63)] = Wb[i];

    float c[2][8][4];
    #pragma unroll
    for (int mt = 0; mt < 2; mt++)
        #pragma unroll
        for (int nt = 0; nt < 8; nt++)
            #pragma unroll
            for (int q = 0; q < 4; q++) c[mt][nt][q] = 0.f;

    mma_mainloop(g_keyHi + (size_t)rowBase*E_, g_keyLo + (size_t)rowBase*E_,
                 g_WkTHi + (size_t)h*128*E_,  g_WkTLo + (size_t)h*128*E_,
                 sbR, c);

    store_C(Cs, c, tid);

    float biasv[8], gamv[8], betv[8], qv[8];
    #pragma unroll
    for (int j = 0; j < 8; j++) {
        const int e = h*128 + tx*8 + j;
        biasv[j] = bk[e]; gamv[j] = gk[e]; betv[j] = Bk[e];
        qv[j] = g_q[bh*128 + tx*8 + j];
    }
    __syncthreads();

    #pragma unroll
    for (int i = 0; i < 8; i++) {
        float vrow[8]; float s = 0.f, sq = 0.f;
        #pragma unroll
        for (int j = 0; j < 8; j++) {
            float v = Cs[(ty*8+i)*132 + tx*8 + j] + biasv[j];
            v = v > 0.f ? v : expm1f(v);
            vrow[j] = v; s += v; sq += v*v;
        }
        #pragma unroll
        for (int o = 1; o < 16; o <<= 1) {
            s  += __shfl_xor_sync(0xffffffffu, s,  o);
            sq += __shfl_xor_sync(0xffffffffu, sq, o);
        }
        const float mu  = s * (1.f/128.f);
        const float var = sq * (1.f/128.f) - mu*mu;
        const float rs  = rsqrtf(var + EPSV);
        const int row = ty*8 + i;
        #pragma unroll
        for (int j = 0; j < 8; j++) {
            float a = (vrow[j]-mu)*rs*gamv[j] + betv[j];
            a *= qv[j];
            aS[row*129 + tx*8 + j] = a;
        }
    }
    __syncthreads();

    // mini-GEMM: 128x64 = aS(128x128) @ WbS(128x64)
    float acc2[8][4];
    #pragma unroll
    for (int i = 0; i < 8; i++)
        #pragma unroll
        for (int j = 0; j < 4; j++) acc2[i][j] = 0.f;
    for (int d = 0; d < 128; d++) {
        const float4 wv = *(const float4*)(WbS + d*68 + tx*4);
        #pragma unroll
        for (int i = 0; i < 8; i++) {
            const float a = aS[(ty*8+i)*129 + d];
            acc2[i][0] += a*wv.x; acc2[i][1] += a*wv.y;
            acc2[i][2] += a*wv.z; acc2[i][3] += a*wv.w;
        }
    }

    float bbv[4], wl1v[4];
    #pragma unroll
    for (int j = 0; j < 4; j++) {
        const int mid = tx*4 + j;
        bbv[j] = bb[mid]; wl1v[j] = Wl1[mid];
    }
    const float bl1v = bl1[0];
    float maskv[8];
    #pragma unroll
    for (int i = 0; i < 8; i++)
        maskv[i] = mask[b*M_ + tile*128 + ty*8 + i];

    float pp[4] = {0.f, 0.f, 0.f, 0.f};
    #pragma unroll
    for (int i = 0; i < 8; i++) {
        float lp = 0.f;
        #pragma unroll
        for (int j = 0; j < 4; j++) {
            float bas = acc2[i][j] + bbv[j];
            bas = bas > 0.f ? bas : 0.f;
            lp += bas * wl1v[j];
            pp[j] += bas * maskv[i];
        }
        #pragma unroll
        for (int o = 1; o < 16; o <<= 1) lp += __shfl_xor_sync(0xffffffffu, lp, o);
        if (tx == 0)
            g_logits[bh*M_ + tile*128 + ty*8 + i] = lp + bl1v;
    }

    __syncthreads();
    float* poolS = WbS;                 // alias after use
    #pragma unroll
    for (int j = 0; j < 4; j++) poolS[ty*64 + tx*4 + j] = pp[j];
    __syncthreads();
    if (tid < 64) {
        float sum = 0.f;
        #pragma unroll
        for (int t = 0; t < 16; t++) sum += poolS[t*64 + tid];
        g_poolpart[(bh*16 + tile)*64 + tid] = sum;
    }
}

// ---------------------------------------------------------------------------
// Kernel 3: V2 path (tensor-core GEMM + GN epilogue)
// smem: staging [0,98304) then Cs[0,67584) after mainloop.
// ---------------------------------------------------------------------------
__global__ void __launch_bounds__(256) k_vpath(
    const float* __restrict__ bv2, const float* __restrict__ gv2,
    const float* __restrict__ Bv2)
{
    extern __shared__ float smf[];
    float* Cs = smf;
    const uint32_t sbR = smem_u32(smf);

    const int tid = threadIdx.x;
    const int tx = tid & 15, ty = tid >> 4;
    const int h = blockIdx.x;
    const int rowBase = blockIdx.y * 128;

    float c[2][8][4];
    #pragma unroll
    for (int mt = 0; mt < 2; mt++)
        #pragma unroll
        for (int nt = 0; nt < 8; nt++)
            #pragma unroll
            for (int q = 0; q < 4; q++) c[mt][nt][q] = 0.f;

    mma_mainloop(g_v2iHi + (size_t)rowBase*E_, g_v2iLo + (size_t)rowBase*E_,
                 g_Wv2THi + (size_t)h*128*E_,  g_Wv2TLo + (size_t)h*128*E_,
                 sbR, c);

    store_C(Cs, c, tid);

    float biasv[8], gamv[8], betv[8];
    #pragma unroll
    for (int j = 0; j < 8; j++) {
        const int e = h*128 + tx*8 + j;
        biasv[j] = bv2[e]; gamv[j] = gv2[e]; betv[j] = Bv2[e];
    }
    __syncthreads();

    #pragma unroll
    for (int i = 0; i < 8; i++) {
        float vrow[8]; float s = 0.f, sq = 0.f;
        #pragma unroll
        for (int j = 0; j < 8; j++) {
            float v = Cs[(ty*8+i)*132 + tx*8 + j] + biasv[j];
            v = v > 0.f ? v : expm1f(v);
            vrow[j] = v; s += v; sq += v*v;
        }
        #pragma unroll
        for (int o = 1; o < 16; o <<= 1) {
            s  += __shfl_xor_sync(0xffffffffu, s,  o);
            sq += __shfl_xor_sync(0xffffffffu, sq, o);
        }
        const float mu  = s * (1.f/128.f);
        const float var = sq * (1.f/128.f) - mu*mu;
        const float rs  = rsqrtf(var + EPSV);
        float4 o0, o1;
        o0.x = (vrow[0]-mu)*rs*gamv[0] + betv[0];
        o0.y = (vrow[1]-mu)*rs*gamv[1] + betv[1];
        o0.z = (vrow[2]-mu)*rs*gamv[2] + betv[2];
        o0.w = (vrow[3]-mu)*rs*gamv[3] + betv[3];
        o1.x = (vrow[4]-mu)*rs*gamv[4] + betv[4];
        o1.y = (vrow[5]-mu)*rs*gamv[5] + betv[5];
        o1.z = (vrow[6]-mu)*rs*gamv[6] + betv[6];
        o1.w = (vrow[7]-mu)*rs*gamv[7] + betv[7];
        float* dst = g_v2 + (size_t)(rowBase + ty*8 + i)*E_ + h*128 + tx*8;
        *(float4*)dst = o0;
        *(float4*)(dst + 4) = o1;
    }
}

// ---------------------------------------------------------------------------
// Kernel 4: masked softmax + pool reduce + alpha_ch (unchanged)
// ---------------------------------------------------------------------------
__global__ void k_softmax_pool(const float* __restrict__ mask,
                               const float* __restrict__ Wl2,
                               const float* __restrict__ bl2)
{
    const int bh = blockIdx.x, b = bh >> 3;
    const int tid = threadIdx.x;
    const int w = tid >> 5, lane = tid & 31;
    __shared__ float red[8];
    __shared__ float poolv[64];

    float lg[8];
    #pragma unroll
    for (int i = 0; i < 8; i++) {
        const int m = tid + i*256;
        const float mk = mask[b*M_ + m];
        const float L = g_logits[bh*M_ + m];
        lg[i] = (mk == 0.f) ? -1e9f : L;
    }
    float mx = lg[0];
    #pragma unroll
    for (int i = 1; i < 8; i++) mx = fmaxf(mx, lg[i]);
    #pragma unroll
    for (int o = 16; o > 0; o >>= 1) mx = fmaxf(mx, __shfl_xor_sync(0xffffffffu, mx, o));
    if (lane == 0) red[w] = mx;
    __syncthreads();
    float bm = red[0];
    #pragma unroll
    for (int i = 1; i < 8; i++) bm = fmaxf(bm, red[i]);

    float sum = 0.f;
    #pragma unroll
    for (int i = 0; i < 8; i++) { lg[i] = __expf(lg[i] - bm); sum += lg[i]; }
    #pragma unroll
    for (int o = 16; o > 0; o >>= 1) sum += __shfl_xor_sync(0xffffffffu, sum, o);
    __syncthreads();
    if (lane == 0) red[w] = sum;
    __syncthreads();
    float ts = 0.f;
    #pragma unroll
    for (int i = 0; i < 8; i++) ts += red[i];
    const float inv = 1.f / ts;
    #pragma unroll
    for (int i = 0; i < 8; i++)
        g_alpha[bh*M_ + tid + i*256] = lg[i] * inv;

    if (tid < 64) {
        float s = 0.f;
        #pragma unroll
        for (int t = 0; t < 16; t++) s += g_poolpart[(bh*16 + t)*64 + tid];
        poolv[tid] = s / g_masksum[b];
    }
    __syncthreads();
    if (tid < 128) {
        float a = bl2[tid];
        #pragma unroll
        for (int mid = 0; mid < 64; mid++) a += poolv[mid] * Wl2[mid*128 + tid];
        g_alpha_ch[bh*128 + tid] = 1.f / (1.f + __expf(-a));
    }
}

// ---------------------------------------------------------------------------
// Kernel 5: v2_agg partials (unchanged)
// ---------------------------------------------------------------------------
__global__ void k_v2agg()
{
    const int blk = blockIdx.x;
    const int bh = blk >> 4, slice = blk & 15;
    const int b = bh >> 3, h = bh & 7;
    const int tid = threadIdx.x;
    __shared__ float al[128];
    al[tid] = g_alpha[bh*M_ + slice*128 + tid];
    __syncthreads();
    const float* base = g_v2 + (size_t)(b*M_ + slice*128)*E_ + h*128 + tid;
    float acc = 0.f;
    #pragma unroll 8
    for (int mm = 0; mm < 128; mm++)
        acc += al[mm] * base[(size_t)mm*E_];
    g_part[blk*128 + tid] = acc;
}

// ---------------------------------------------------------------------------
// Kernel 6: final combine (unchanged)
// ---------------------------------------------------------------------------
__global__ void k_final(float* __restrict__ out)
{
    const int i = blockIdx.x*256 + threadIdx.x;
    const int bh = i >> 7, d = i & 127;
    float s = 0.f;
    #pragma unroll
    for (int t = 0; t < 16; t++) s += g_part[(bh*16 + t)*128 + d];
    out[i] = g_v1[i] * s * g_alpha_ch[i];
}

// ---------------------------------------------------------------------------
extern "C" void kernel_launch(void* const* d_in, const int* in_sizes, int n_in,
                              void* d_out, int out_size)
{
    const float* query  = (const float*)d_in[0];
    const float* key    = (const float*)d_in[1];
    const float* mask   = (const float*)d_in[2];
    const float* value1 = (const float*)d_in[3];
    const float* value2 = (const float*)d_in[4];
    const float* Wq  = (const float*)d_in[5];
    const float* bq  = (const float*)d_in[6];
    const float* gq  = (const float*)d_in[7];
    const float* Bq  = (const float*)d_in[8];
    const float* Wk  = (const float*)d_in[9];
    const float* bk  = (const float*)d_in[10];
    const float* gk  = (const float*)d_in[11];
    const float* Bk  = (const float*)d_in[12];
    const float* Wv1 = (const float*)d_in[13];
    const float* bv1 = (const float*)d_in[14];
    const float* gv1 = (const float*)d_in[15];
    const float* Bv1 = (const float*)d_in[16];
    const float* Wv2 = (const float*)d_in[17];
    const float* bv2 = (const float*)d_in[18];
    const float* gv2 = (const float*)d_in[19];
    const float* Bv2 = (const float*)d_in[20];
    const float* Wb  = (const float*)d_in[21];
    const float* bb  = (const float*)d_in[22];
    const float* Wl1 = (const float*)d_in[23];
    const float* bl1 = (const float*)d_in[24];
    const float* Wl2 = (const float*)d_in[25];
    const float* bl2 = (const float*)d_in[26];
    float* out = (float*)d_out;

    const int SMEM_KP = (16896 + 16512 + 8704) * 4;   // 168448 B
    const int SMEM_VP = 3 * 32768;                    // 98304 B (staging)
    cudaFuncSetAttribute(k_kpath, cudaFuncAttributeMaxDynamicSharedMemorySize, SMEM_KP);
    cudaFuncSetAttribute(k_vpath, cudaFuncAttributeMaxDynamicSharedMemorySize, SMEM_VP);

    k_cvt_inputs<<<dim3(16384, 2), 256>>>(key, value2);
    k_transpose<<<dim3(32,32,2), dim3(32,8)>>>(Wk, Wv2);
    k_smallproj<<<32, 256>>>(query, value1, mask,
                             Wq, bq, gq, Bq, Wv1, bv1, gv1, Bv1);

    dim3 gbig(8, 256);
    k_kpath<<<gbig, 256, SMEM_KP>>>(bk, gk, Bk, mask, Wb, bb, Wl1, bl1);
    k_vpath<<<gbig, 256, SMEM_VP>>>(bv2, gv2, Bv2);
    k_softmax_pool<<<128, 256>>>(mask, Wl2, bl2);
    k_v2agg<<<2048, 128>>>();
    k_final<<<64, 256>>>(out);

    (void)in_sizes; (void)n_in; (void)out_size;
}

// round 11
// speedup vs baseline: 1.1025x; 1.1025x over previous
#include <cuda_runtime.h>
#include <cuda_bf16.h>
#include <math.h>
#include <stdint.h>

#define B_   16
#define M_   2048
#define E_   1024
#define H_   8
#define D_   128
#define MID_ 64
#define EPSV 1e-3f

// ---------------- scratch (device globals) ---------------------------------
__device__ float g_q[B_*H_*D_];
__device__ float g_v1[B_*H_*D_];
__device__ float g_masksum[B_];
__device__ float g_logits[B_*H_*M_];
__device__ float g_alpha[B_*H_*M_];
__device__ float g_poolpart[B_*H_*16*MID_];
__device__ float g_alpha_ch[B_*H_*D_];
__device__ float g_part[B_*H_*16*D_];
__device__ float g_v2[(size_t)B_*M_*E_];                 // 128 MiB normalized v2
// pre-converted bf16 hi/lo operands
__device__ __nv_bfloat16 g_keyHi[(size_t)B_*M_*E_];
__device__ __nv_bfloat16 g_keyLo[(size_t)B_*M_*E_];
__device__ __nv_bfloat16 g_v2iHi[(size_t)B_*M_*E_];
__device__ __nv_bfloat16 g_v2iLo[(size_t)B_*M_*E_];
__device__ __nv_bfloat16 g_WkTHi[E_*E_];                 // Wk^T  [n][k]
__device__ __nv_bfloat16 g_WkTLo[E_*E_];
__device__ __nv_bfloat16 g_Wv2THi[E_*E_];                // Wv2^T [n][k]
__device__ __nv_bfloat16 g_Wv2TLo[E_*E_];

// ---------------- helpers ---------------------------------------------------
__device__ __forceinline__ uint32_t smem_u32(const void* p) {
    uint32_t a;
    asm("{ .reg .u64 t; cvta.to.shared.u64 t, %1; cvt.u32.u64 %0, t; }"
        : "=r"(a) : "l"(p));
    return a;
}
__device__ __forceinline__ uint32_t packbf(__nv_bfloat16 a, __nv_bfloat16 b) {
    return (uint32_t)__bfloat16_as_ushort(a) |
           ((uint32_t)__bfloat16_as_ushort(b) << 16);
}

#define LDSM4(r0,r1,r2,r3,a) \
    asm volatile("ldmatrix.sync.aligned.m8n8.x4.shared.b16 {%0,%1,%2,%3}, [%4];" \
        : "=r"(r0), "=r"(r1), "=r"(r2), "=r"(r3) : "r"(a))

#define MMA16816(c, a, b0, b1) \
    asm volatile("mma.sync.aligned.m16n8k16.row.col.f32.bf16.bf16.f32 " \
        "{%0,%1,%2,%3},{%4,%5,%6,%7},{%8,%9},{%0,%1,%2,%3};" \
        : "+f"((c)[0]), "+f"((c)[1]), "+f"((c)[2]), "+f"((c)[3]) \
        : "r"((a)[0]), "r"((a)[1]), "r"((a)[2]), "r"((a)[3]), "r"(b0), "r"(b1))

#define CP16(dst, src) \
    asm volatile("cp.async.ca.shared.global [%0], [%1], 16;" \
                 :: "r"(dst), "l"(src) : "memory")
#define CP_COMMIT() asm volatile("cp.async.commit_group;" ::: "memory")
#define CP_WAIT(n)  asm volatile("cp.async.wait_group %0;" :: "n"(n) : "memory")

// staging tile layout: [128 rows][32 bf16] = 64B/row, XOR swizzle on 16B groups
__device__ __forceinline__ uint32_t sw_off(int r, int g) {
    return (uint32_t)(r*64 + ((g ^ ((r >> 1) & 3)) << 4));
}

// issue one chunk (K=32 slice) of A hi/lo + B hi/lo via cp.async
// stage layout: AHi +0, ALo +8192, BHi +16384, BLo +24576
__device__ __forceinline__ void issue_chunk(
    const __nv_bfloat16* __restrict__ AHi, const __nv_bfloat16* __restrict__ ALo,
    const __nv_bfloat16* __restrict__ BHi, const __nv_bfloat16* __restrict__ BLo,
    int ck, uint32_t st, int tid)
{
    #pragma unroll
    for (int u = 0; u < 2; u++) {
        const int idx = tid*2 + u;            // 0..511 16B-groups per tile
        const int r = idx >> 2, g = idx & 3;
        const uint32_t off = sw_off(r, g);
        const size_t gofs = (size_t)r*E_ + ck*32 + g*8;
        CP16(st +         off, AHi + gofs);
        CP16(st +  8192 + off, ALo + gofs);
        CP16(st + 16384 + off, BHi + gofs);
        CP16(st + 24576 + off, BLo + gofs);
    }
}

// ---------------------------------------------------------------------------
// split-bf16 tensor-core mainloop: C[128][128] = A[128x1024] @ BT[128x1024]^T
// 256 threads, warp w: wm=w&3 (32 rows), wn=w>>2 (64 cols); BK=32, 2 cp.async
// stages at sbR + s*32768. B fragments loaded per-nb to cap register liveness.
// ---------------------------------------------------------------------------
__device__ __forceinline__ void mma_mainloop(
    const __nv_bfloat16* __restrict__ AHi, const __nv_bfloat16* __restrict__ ALo,
    const __nv_bfloat16* __restrict__ BHi, const __nv_bfloat16* __restrict__ BLo,
    uint32_t sbR, float c[2][8][4])
{
    const int tid = threadIdx.x;
    const int lane = tid & 31, w = tid >> 5;
    const int wm = w & 3, wn = w >> 2;
    const int qi = lane >> 3, ii = lane & 7;

    issue_chunk(AHi, ALo, BHi, BLo, 0, sbR, tid); CP_COMMIT();

    for (int ck = 0; ck < 32; ck++) {
        if (ck + 1 < 32) {
            issue_chunk(AHi, ALo, BHi, BLo, ck + 1,
                        sbR + ((ck + 1) & 1)*32768, tid);
            CP_COMMIT();
            CP_WAIT(1);
        } else {
            CP_WAIT(0);
        }
        __syncthreads();

        const uint32_t st = sbR + (ck & 1)*32768;
        #pragma unroll
        for (int p = 0; p < 2; p++) {
            uint32_t ah[2][4], al[2][4];
            #pragma unroll
            for (int mt = 0; mt < 2; mt++) {
                const int r = wm*32 + mt*16 + ii + ((qi & 1) << 3);
                const int g = 2*p + (qi >> 1);
                const uint32_t off = sw_off(r, g);
                LDSM4(ah[mt][0], ah[mt][1], ah[mt][2], ah[mt][3], st + off);
                LDSM4(al[mt][0], al[mt][1], al[mt][2], al[mt][3], st + 8192 + off);
            }
            #pragma unroll
            for (int nb = 0; nb < 4; nb++) {
                uint32_t bh[4], bl[4];
                const int r = wn*64 + nb*16 + ii + ((qi >> 1) << 3);
                const int g = 2*p + (qi & 1);
                const uint32_t off = sw_off(r, g);
                LDSM4(bh[0], bh[1], bh[2], bh[3], st + 16384 + off);
                LDSM4(bl[0], bl[1], bl[2], bl[3], st + 24576 + off);
                #pragma unroll
                for (int mt = 0; mt < 2; mt++)
                    #pragma unroll
                    for (int half = 0; half < 2; half++) {
                        float* cc = c[mt][nb*2 + half];
                        MMA16816(cc, ah[mt], bh[half*2], bh[half*2+1]);
                        MMA16816(cc, ah[mt], bl[half*2], bl[half*2+1]);
                        MMA16816(cc, al[mt], bh[half*2], bh[half*2+1]);
                    }
            }
        }
        __syncthreads();
    }
}

// fragment-direct GN stats: elu(c+bias) in-place, then per-row mu/rs via
// [128][8] float2 slots. Returns mu[mt][half], rs[mt][half] per thread.
__device__ __forceinline__ void gn_stats(
    float c[2][8][4], const float* biasS, float2* slotS,
    float mu[2][2], float rs[2][2])
{
    const int tid = threadIdx.x;
    const int lane = tid & 31, w = tid >> 5;
    const int wm = w & 3, wn = w >> 2;
    const int rq = lane >> 2, cq = (lane & 3)*2;
    const int slot = wn*4 + (lane & 3);

    float s[2][2]  = {{0.f,0.f},{0.f,0.f}};
    float sq[2][2] = {{0.f,0.f},{0.f,0.f}};
    #pragma unroll
    for (int mt = 0; mt < 2; mt++)
        #pragma unroll
        for (int nt = 0; nt < 8; nt++) {
            const int n = wn*64 + nt*8 + cq;
            const float b0 = biasS[n], b1 = biasS[n+1];
            float x0 = c[mt][nt][0] + b0; x0 = x0 > 0.f ? x0 : expm1f(x0);
            float x1 = c[mt][nt][1] + b1; x1 = x1 > 0.f ? x1 : expm1f(x1);
            float x2 = c[mt][nt][2] + b0; x2 = x2 > 0.f ? x2 : expm1f(x2);
            float x3 = c[mt][nt][3] + b1; x3 = x3 > 0.f ? x3 : expm1f(x3);
            c[mt][nt][0] = x0; c[mt][nt][1] = x1;
            c[mt][nt][2] = x2; c[mt][nt][3] = x3;
            s[mt][0] += x0 + x1;  sq[mt][0] += x0*x0 + x1*x1;
            s[mt][1] += x2 + x3;  sq[mt][1] += x2*x2 + x3*x3;
        }
    #pragma unroll
    for (int mt = 0; mt < 2; mt++)
        #pragma unroll
        for (int half = 0; half < 2; half++) {
            const int m = wm*32 + mt*16 + half*8 + rq;
            slotS[m*8 + slot] = make_float2(s[mt][half], sq[mt][half]);
        }
    __syncthreads();
    #pragma unroll
    for (int mt = 0; mt < 2; mt++)
        #pragma unroll
        for (int half = 0; half < 2; half++) {
            const int m = wm*32 + mt*16 + half*8 + rq;
            float S = 0.f, Q = 0.f;
            #pragma unroll
            for (int k = 0; k < 8; k++) {
                const float2 v = slotS[m*8 + k];
                S += v.x; Q += v.y;
            }
            const float muv = S * (1.f/128.f);
            const float var = Q * (1.f/128.f) - muv*muv;
            mu[mt][half] = muv;
            rs[mt][half] = rsqrtf(var + EPSV);
        }
}

// ---------------------------------------------------------------------------
// Kernel P: convert key/value2 fp32 -> bf16 hi/lo. grid (16384, 2), 256 thr.
// ---------------------------------------------------------------------------
__global__ void k_cvt_inputs(const float* __restrict__ key,
                             const float* __restrict__ value2)
{
    const int z = blockIdx.y;
    const float* src      = z ? value2 : key;
    __nv_bfloat16* hiD    = z ? g_v2iHi : g_keyHi;
    __nv_bfloat16* loD    = z ? g_v2iLo : g_keyLo;
    const size_t i = ((size_t)blockIdx.x*256 + threadIdx.x) * 8;
    const float4 v0 = *(const float4*)(src + i);
    const float4 v1 = *(const float4*)(src + i + 4);
    const float f[8] = {v0.x, v0.y, v0.z, v0.w, v1.x, v1.y, v1.z, v1.w};
    uint32_t hw[4], lw[4];
    #pragma unroll
    for (int j = 0; j < 4; j++) {
        const __nv_bfloat16 h0 = __float2bfloat16(f[2*j]);
        const __nv_bfloat16 h1 = __float2bfloat16(f[2*j+1]);
        hw[j] = packbf(h0, h1);
        lw[j] = packbf(__float2bfloat16(f[2*j]   - __bfloat162float(h0)),
                       __float2bfloat16(f[2*j+1] - __bfloat162float(h1)));
    }
    *(uint4*)(hiD + i) = make_uint4(hw[0], hw[1], hw[2], hw[3]);
    *(uint4*)(loD + i) = make_uint4(lw[0], lw[1], lw[2], lw[3]);
}

// ---------------------------------------------------------------------------
// Kernel 0: weight transpose + bf16 hi/lo split. grid (32,32,2), block (32,8)
// ---------------------------------------------------------------------------
__global__ void k_transpose(const float* __restrict__ Wk,
                            const float* __restrict__ Wv2)
{
    __shared__ float t[32][33];
    const int z = blockIdx.z;
    const float* S        = (z == 0) ? Wk : Wv2;
    __nv_bfloat16* hiD    = (z == 0) ? g_WkTHi : g_Wv2THi;
    __nv_bfloat16* loD    = (z == 0) ? g_WkTLo : g_Wv2TLo;
    const int r0 = blockIdx.y * 32, c0 = blockIdx.x * 32;
    const int tx = threadIdx.x, ty = threadIdx.y;
    #pragma unroll
    for (int i = 0; i < 4; i++)
        t[ty + 8*i][tx] = S[(size_t)(r0 + ty + 8*i)*E_ + c0 + tx];
    __syncthreads();
    #pragma unroll
    for (int i = 0; i < 4; i++) {
        const float x = t[tx][ty + 8*i];
        const __nv_bfloat16 h = __float2bfloat16(x);
        const size_t idx = (size_t)(c0 + ty + 8*i)*E_ + r0 + tx;
        hiD[idx] = h;
        loD[idx] = __float2bfloat16(x - __bfloat162float(h));
    }
}

// ---------------------------------------------------------------------------
// Kernel 1: q/v1 small projections + masksum (unchanged)
// ---------------------------------------------------------------------------
__global__ void k_smallproj(const float* __restrict__ query,
                            const float* __restrict__ value1,
                            const float* __restrict__ mask,
                            const float* __restrict__ Wq, const float* __restrict__ bq,
                            const float* __restrict__ gq, const float* __restrict__ Bq,
                            const float* __restrict__ Wv1, const float* __restrict__ bv1,
                            const float* __restrict__ gv1, const float* __restrict__ Bv1)
{
    __shared__ float xs[E_];
    __shared__ float ys[E_];
    __shared__ float red[8];
    const int blk   = blockIdx.x;
    const int which = blk >> 4;
    const int r     = blk & 15;
    const float* x    = which ? value1 : query;
    const float* W    = which ? Wv1 : Wq;
    const float* bias = which ? bv1 : bq;
    const float* gam  = which ? gv1 : gq;
    const float* bet  = which ? Bv1 : Bq;
    float* dst        = which ? g_v1 : g_q;
    const int tid = threadIdx.x;

    #pragma unroll
    for (int c = 0; c < 4; c++) xs[tid + 256*c] = x[r*E_ + tid + 256*c];
    __syncthreads();

    float a0 = bias[tid], a1 = bias[tid+256], a2 = bias[tid+512], a3 = bias[tid+768];
    #pragma unroll 4
    for (int k = 0; k < E_; k++) {
        const float xv = xs[k];
        const float* wr = W + (size_t)k*E_ + tid;
        a0 += xv*wr[0]; a1 += xv*wr[256]; a2 += xv*wr[512]; a3 += xv*wr[768];
    }
    a0 = a0 > 0.f ? a0 : expm1f(a0);
    a1 = a1 > 0.f ? a1 : expm1f(a1);
    a2 = a2 > 0.f ? a2 : expm1f(a2);
    a3 = a3 > 0.f ? a3 : expm1f(a3);
    ys[tid] = a0; ys[tid+256] = a1; ys[tid+512] = a2; ys[tid+768] = a3;
    __syncthreads();

    const int w = tid >> 5, lane = tid & 31;
    float v[4]; float s = 0.f, sq = 0.f;
    #pragma unroll
    for (int c = 0; c < 4; c++) {
        v[c] = ys[w*128 + lane + 32*c];
        s += v[c]; sq += v[c]*v[c];
    }
    #pragma unroll
    for (int o = 16; o > 0; o >>= 1) {
        s  += __shfl_xor_sync(0xffffffffu, s,  o);
        sq += __shfl_xor_sync(0xffffffffu, sq, o);
    }
    const float mu  = s * (1.f/128.f);
    const float var = sq * (1.f/128.f) - mu*mu;
    const float rs  = rsqrtf(var + EPSV);
    #pragma unroll
    for (int c = 0; c < 4; c++) {
        const int d = lane + 32*c;
        const int e = w*128 + d;
        dst[(r*8 + w)*128 + d] = (v[c]-mu)*rs*gam[e] + bet[e];
    }

    if (which == 0) {
        float ms = 0.f;
        #pragma unroll
        for (int i = 0; i < 8; i++) ms += mask[r*M_ + tid + 256*i];
        #pragma unroll
        for (int o = 16; o > 0; o >>= 1) ms += __shfl_xor_sync(0xffffffffu, ms, o);
        if (lane == 0) red[w] = ms;
        __syncthreads();
        if (tid == 0) {
            float t = 0.f;
            #pragma unroll
            for (int i = 0; i < 8; i++) t += red[i];
            g_masksum[r] = t;
        }
    }
}

// ---------------------------------------------------------------------------
// Kernel 2: K path. smem layout (floats from smc):
//  [0,3072)B params: biasS 0, gamS 512, betS 1024, qS 1536, maskS 2048,
//                    Wl1S 2560, bbS 2816
//  [3072, 3072+74752)B region R: staging 2x32768 during mainloop;
//        after: slotS [128][8] float2 (8192B) at R+0, aS fp32 pitch130 at R+8192
//  [77824, 112640)B WbS fp32 pitch 68
// ---------------------------------------------------------------------------
__global__ void __launch_bounds__(256, 2) k_kpath(
    const float* __restrict__ bk,  const float* __restrict__ gk,
    const float* __restrict__ Bk,  const float* __restrict__ mask,
    const float* __restrict__ Wb,  const float* __restrict__ bb,
    const float* __restrict__ Wl1, const float* __restrict__ bl1)
{
    extern __shared__ char smc[];
    const uint32_t sbR = smem_u32(smc) + 3072;

    float*  biasS = (float*)(smc + 0);
    float*  gamS  = (float*)(smc + 512);
    float*  betS  = (float*)(smc + 1024);
    float*  qS    = (float*)(smc + 1536);
    float*  maskS = (float*)(smc + 2048);
    float*  Wl1S  = (float*)(smc + 2560);
    float*  bbS   = (float*)(smc + 2816);
    float2* slotS = (float2*)(smc + 3072);
    float*  aS    = (float*)(smc + 3072 + 8192);      // pitch 130
    float*  WbS   = (float*)(smc + 77824);            // pitch 68

    const int tid = threadIdx.x;
    const int h = blockIdx.x;
    const int rowBase = blockIdx.y * 128;
    const int b    = rowBase >> 11;
    const int tile = (rowBase >> 7) & 15;
    const int bh = b*8 + h;

    if (tid < 128) {
        const int e = h*128 + tid;
        biasS[tid] = bk[e]; gamS[tid] = gk[e]; betS[tid] = Bk[e];
        qS[tid]    = g_q[bh*128 + tid];
        maskS[tid] = mask[b*M_ + tile*128 + tid];
    } else if (tid < 192) {
        Wl1S[tid-128] = Wl1[tid-128]; bbS[tid-128] = bb[tid-128];
    }
    for (int i = tid; i < 128*64; i += 256)
        WbS[(i>>6)*68 + (i&63)] = Wb[i];
    __syncthreads();

    float c[2][8][4];
    #pragma unroll
    for (int mt = 0; mt < 2; mt++)
        #pragma unroll
        for (int nt = 0; nt < 8; nt++)
            #pragma unroll
            for (int q = 0; q < 4; q++) c[mt][nt][q] = 0.f;

    mma_mainloop(g_keyHi + (size_t)rowBase*E_, g_keyLo + (size_t)rowBase*E_,
                 g_WkTHi + (size_t)h*128*E_,  g_WkTLo + (size_t)h*128*E_,
                 sbR, c);

    // fragment-direct GN + q*; write aS
    float mu[2][2], rs[2][2];
    gn_stats(c, biasS, slotS, mu, rs);

    {
        const int lane = tid & 31, w = tid >> 5;
        const int wm = w & 3, wn = w >> 2;
        const int rq = lane >> 2, cq = (lane & 3)*2;
        #pragma unroll
        for (int mt = 0; mt < 2; mt++)
            #pragma unroll
            for (int nt = 0; nt < 8; nt++) {
                const int n = wn*64 + nt*8 + cq;
                const float g0 = gamS[n], g1 = gamS[n+1];
                const float t0 = betS[n], t1 = betS[n+1];
                const float q0 = qS[n],  q1 = qS[n+1];
                #pragma unroll
                for (int half = 0; half < 2; half++) {
                    const int m = wm*32 + mt*16 + half*8 + rq;
                    const float a0 = ((c[mt][nt][half*2]   - mu[mt][half])*rs[mt][half]*g0 + t0) * q0;
                    const float a1 = ((c[mt][nt][half*2+1] - mu[mt][half])*rs[mt][half]*g1 + t1) * q1;
                    *(float2*)(aS + m*130 + n) = make_float2(a0, a1);
                }
            }
    }
    __syncthreads();

    // mini-GEMM: 128x64 = aS(128x128) @ WbS(128x64); thread (tx,ty)
    const int tx = tid & 15, ty = tid >> 4;
    float acc2[8][4];
    #pragma unroll
    for (int i = 0; i < 8; i++)
        #pragma unroll
        for (int j = 0; j < 4; j++) acc2[i][j] = 0.f;
    for (int d = 0; d < 128; d++) {
        const float4 wv = *(const float4*)(WbS + d*68 + tx*4);
        #pragma unroll
        for (int i = 0; i < 8; i++) {
            const float a = aS[(ty*8+i)*130 + d];
            acc2[i][0] += a*wv.x; acc2[i][1] += a*wv.y;
            acc2[i][2] += a*wv.z; acc2[i][3] += a*wv.w;
        }
    }

    float bbv[4], wl1v[4];
    #pragma unroll
    for (int j = 0; j < 4; j++) {
        const int mid = tx*4 + j;
        bbv[j] = bbS[mid]; wl1v[j] = Wl1S[mid];
    }
    const float bl1v = bl1[0];
    float maskv[8];
    #pragma unroll
    for (int i = 0; i < 8; i++) maskv[i] = maskS[ty*8 + i];

    float pp[4] = {0.f, 0.f, 0.f, 0.f};
    #pragma unroll
    for (int i = 0; i < 8; i++) {
        float lp = 0.f;
        #pragma unroll
        for (int j = 0; j < 4; j++) {
            float bas = acc2[i][j] + bbv[j];
            bas = bas > 0.f ? bas : 0.f;
            lp += bas * wl1v[j];
            pp[j] += bas * maskv[i];
        }
        #pragma unroll
        for (int o = 1; o < 16; o <<= 1) lp += __shfl_xor_sync(0xffffffffu, lp, o);
        if (tx == 0)
            g_logits[bh*M_ + tile*128 + ty*8 + i] = lp + bl1v;
    }

    __syncthreads();
    float* poolS = (float*)slotS;       // [16][64], aliases dead slot region
    #pragma unroll
    for (int j = 0; j < 4; j++) poolS[ty*64 + tx*4 + j] = pp[j];
    __syncthreads();
    if (tid < 64) {
        float sum = 0.f;
        #pragma unroll
        for (int t = 0; t < 16; t++) sum += poolS[t*64 + tid];
        g_poolpart[(bh*16 + tile)*64 + tid] = sum;
    }
}

// ---------------------------------------------------------------------------
// Kernel 3: V2 path. smem: params [0,1536)B; region at 1536: staging 2x32768
// (slotS aliases its head after mainloop). Total 67072 B.
// ---------------------------------------------------------------------------
__global__ void __launch_bounds__(256, 2) k_vpath(
    const float* __restrict__ bv2, const float* __restrict__ gv2,
    const float* __restrict__ Bv2)
{
    extern __shared__ char smc[];
    const uint32_t sbR = smem_u32(smc) + 1536;

    float*  biasS = (float*)(smc + 0);
    float*  gamS  = (float*)(smc + 512);
    float*  betS  = (float*)(smc + 1024);
    float2* slotS = (float2*)(smc + 1536);

    const int tid = threadIdx.x;
    const int h = blockIdx.x;
    const int rowBase = blockIdx.y * 128;

    if (tid < 128) {
        const int e = h*128 + tid;
        biasS[tid] = bv2[e]; gamS[tid] = gv2[e]; betS[tid] = Bv2[e];
    }
    __syncthreads();

    float c[2][8][4];
    #pragma unroll
    for (int mt = 0; mt < 2; mt++)
        #pragma unroll
        for (int nt = 0; nt < 8; nt++)
            #pragma unroll
            for (int q = 0; q < 4; q++) c[mt][nt][q] = 0.f;

    mma_mainloop(g_v2iHi + (size_t)rowBase*E_, g_v2iLo + (size_t)rowBase*E_,
                 g_Wv2THi + (size_t)h*128*E_,  g_Wv2TLo + (size_t)h*128*E_,
                 sbR, c);

    float mu[2][2], rs[2][2];
    gn_stats(c, biasS, slotS, mu, rs);

    const int lane = tid & 31, w = tid >> 5;
    const int wm = w & 3, wn = w >> 2;
    const int rq = lane >> 2, cq = (lane & 3)*2;
    #pragma unroll
    for (int mt = 0; mt < 2; mt++)
        #pragma unroll
        for (int nt = 0; nt < 8; nt++) {
            const int n = wn*64 + nt*8 + cq;
            const float g0 = gamS[n], g1 = gamS[n+1];
            const float t0 = betS[n], t1 = betS[n+1];
            #pragma unroll
            for (int half = 0; half < 2; half++) {
                const int m = wm*32 + mt*16 + half*8 + rq;
                const float o0 = (c[mt][nt][half*2]   - mu[mt][half])*rs[mt][half]*g0 + t0;
                const float o1 = (c[mt][nt][half*2+1] - mu[mt][half])*rs[mt][half]*g1 + t1;
                *(float2*)(g_v2 + (size_t)(rowBase + m)*E_ + h*128 + n) =
                    make_float2(o0, o1);
            }
        }
}

// ---------------------------------------------------------------------------
// Kernel 4: masked softmax + pool reduce + alpha_ch (unchanged)
// ---------------------------------------------------------------------------
__global__ void k_softmax_pool(const float* __restrict__ mask,
                               const float* __restrict__ Wl2,
                               const float* __restrict__ bl2)
{
    const int bh = blockIdx.x, b = bh >> 3;
    const int tid = threadIdx.x;
    const int w = tid >> 5, lane = tid & 31;
    __shared__ float red[8];
    __shared__ float poolv[64];

    float lg[8];
    #pragma unroll
    for (int i = 0; i < 8; i++) {
        const int m = tid + i*256;
        const float mk = mask[b*M_ + m];
        const float L = g_logits[bh*M_ + m];
        lg[i] = (mk == 0.f) ? -1e9f : L;
    }
    float mx = lg[0];
    #pragma unroll
    for (int i = 1; i < 8; i++) mx = fmaxf(mx, lg[i]);
    #pragma unroll
    for (int o = 16; o > 0; o >>= 1) mx = fmaxf(mx, __shfl_xor_sync(0xffffffffu, mx, o));
    if (lane == 0) red[w] = mx;
    __syncthreads();
    float bm = red[0];
    #pragma unroll
    for (int i = 1; i < 8; i++) bm = fmaxf(bm, red[i]);

    float sum = 0.f;
    #pragma unroll
    for (int i = 0; i < 8; i++) { lg[i] = __expf(lg[i] - bm); sum += lg[i]; }
    #pragma unroll
    for (int o = 16; o > 0; o >>= 1) sum += __shfl_xor_sync(0xffffffffu, sum, o);
    __syncthreads();
    if (lane == 0) red[w] = sum;
    __syncthreads();
    float ts = 0.f;
    #pragma unroll
    for (int i = 0; i < 8; i++) ts += red[i];
    const float inv = 1.f / ts;
    #pragma unroll
    for (int i = 0; i < 8; i++)
        g_alpha[bh*M_ + tid + i*256] = lg[i] * inv;

    if (tid < 64) {
        float s = 0.f;
        #pragma unroll
        for (int t = 0; t < 16; t++) s += g_poolpart[(bh*16 + t)*64 + tid];
        poolv[tid] = s / g_masksum[b];
    }
    __syncthreads();
    if (tid < 128) {
        float a = bl2[tid];
        #pragma unroll
        for (int mid = 0; mid < 64; mid++) a += poolv[mid] * Wl2[mid*128 + tid];
        g_alpha_ch[bh*128 + tid] = 1.f / (1.f + __expf(-a));
    }
}

// ---------------------------------------------------------------------------
// Kernel 5: v2_agg partials (unchanged)
// ---------------------------------------------------------------------------
__global__ void k_v2agg()
{
    const int blk = blockIdx.x;
    const int bh = blk >> 4, slice = blk & 15;
    const int b = bh >> 3, h = bh & 7;
    const int tid = threadIdx.x;
    __shared__ float al[128];
    al[tid] = g_alpha[bh*M_ + slice*128 + tid];
    __syncthreads();
    const float* base = g_v2 + (size_t)(b*M_ + slice*128)*E_ + h*128 + tid;
    float acc = 0.f;
    #pragma unroll 8
    for (int mm = 0; mm < 128; mm++)
        acc += al[mm] * base[(size_t)mm*E_];
    g_part[blk*128 + tid] = acc;
}

// ---------------------------------------------------------------------------
// Kernel 6: final combine (unchanged)
// ---------------------------------------------------------------------------
__global__ void k_final(float* __restrict__ out)
{
    const int i = blockIdx.x*256 + threadIdx.x;
    const int bh = i >> 7, d = i & 127;
    float s = 0.f;
    #pragma unroll
    for (int t = 0; t < 16; t++) s += g_part[(bh*16 + t)*128 + d];
    out[i] = g_v1[i] * s * g_alpha_ch[i];
}

// ---------------------------------------------------------------------------
extern "C" void kernel_launch(void* const* d_in, const int* in_sizes, int n_in,
                              void* d_out, int out_size)
{
    const float* query  = (const float*)d_in[0];
    const float* key    = (const float*)d_in[1];
    const float* mask   = (const float*)d_in[2];
    const float* value1 = (const float*)d_in[3];
    const float* value2 = (const float*)d_in[4];
    const float* Wq  = (const float*)d_in[5];
    const float* bq  = (const float*)d_in[6];
    const float* gq  = (const float*)d_in[7];
    const float* Bq  = (const float*)d_in[8];
    const float* Wk  = (const float*)d_in[9];
    const float* bk  = (const float*)d_in[10];
    const float* gk  = (const float*)d_in[11];
    const float* Bk  = (const float*)d_in[12];
    const float* Wv1 = (const float*)d_in[13];
    const float* bv1 = (const float*)d_in[14];
    const float* gv1 = (const float*)d_in[15];
    const float* Bv1 = (const float*)d_in[16];
    const float* Wv2 = (const float*)d_in[17];
    const float* bv2 = (const float*)d_in[18];
    const float* gv2 = (const float*)d_in[19];
    const float* Bv2 = (const float*)d_in[20];
    const float* Wb  = (const float*)d_in[21];
    const float* bb  = (const float*)d_in[22];
    const float* Wl1 = (const float*)d_in[23];
    const float* bl1 = (const float*)d_in[24];
    const float* Wl2 = (const float*)d_in[25];
    const float* bl2 = (const float*)d_in[26];
    float* out = (float*)d_out;

    const int SMEM_KP = 112640;   // 3072 + 74752 + 34816
    const int SMEM_VP = 67072;    // 1536 + 65536
    cudaFuncSetAttribute(k_kpath, cudaFuncAttributeMaxDynamicSharedMemorySize, SMEM_KP);
    cudaFuncSetAttribute(k_vpath, cudaFuncAttributeMaxDynamicSharedMemorySize, SMEM_VP);

    k_cvt_inputs<<<dim3(16384, 2), 256>>>(key, value2);
    k_transpose<<<dim3(32,32,2), dim3(32,8)>>>(Wk, Wv2);
    k_smallproj<<<32, 256>>>(query, value1, mask,
                             Wq, bq, gq, Bq, Wv1, bv1, gv1, Bv1);

    dim3 gbig(8, 256);
    k_kpath<<<gbig, 256, SMEM_KP>>>(bk, gk, Bk, mask, Wb, bb, Wl1, bl1);
    k_vpath<<<gbig, 256, SMEM_VP>>>(bv2, gv2, Bv2);
    k_softmax_pool<<<128, 256>>>(mask, Wl2, bl2);
    k_v2agg<<<2048, 128>>>();
    k_final<<<64, 256>>>(out);

    (void)in_sizes; (void)n_in; (void)out_size;
}